// round 13
// baseline (speedup 1.0000x reference)
#include <cuda_runtime.h>
#include <cuda_fp16.h>
#include <cuda_bf16.h>
#include <math.h>

#define NU 50000
#define NI 50000
#define NN 100000
#define NE 1600000
#define NP 200000
#define H  64
#define SCAN_NBLK ((NN + 1023) / 1024)   // 98

// ---------------- device scratch ----------------
__device__ int   g_ocnt[NN];
__device__ int   g_icnt[NN];
__device__ float g_onorm[NN];
__device__ float g_innorm[NN];
__device__ float g_rodeg[NN];               // sqrt(max(out_deg,1))
__device__ int   g_off[NN];
__device__ int   g_cur[NN];
__device__ int   g_bsum[SCAN_NBLK];
__device__ float2 g_cpair[NE];              // (src as int bits, onorm[src])
__device__ float g_e0[(size_t)NN * H];
__device__ __half2 g_e0h[(size_t)NN * 32];      // fp16 mirror of e0 (gather reads)
__device__ float g_agg0s[(size_t)NN * H];   // layer-1 out, prescaled by onorm (fp32)
__device__ __half2 g_agg0sh[(size_t)NN * 32];   // fp16 mirror (gather reads)
__device__ float g_xu[(size_t)NU * H];
__device__ float g_xi[(size_t)NI * H];

// ---------------- bf16 mma helper ----------------
__device__ __forceinline__ void mma_bf16(float c[4],
                                         unsigned a0, unsigned a1, unsigned a2, unsigned a3,
                                         unsigned b0, unsigned b1) {
    asm volatile(
        "mma.sync.aligned.m16n8k16.row.col.f32.bf16.bf16.f32 "
        "{%0,%1,%2,%3},{%4,%5,%6,%7},{%8,%9},{%0,%1,%2,%3};"
        : "+f"(c[0]), "+f"(c[1]), "+f"(c[2]), "+f"(c[3])
        : "r"(a0), "r"(a1), "r"(a2), "r"(a3), "r"(b0), "r"(b1));
}

// ---------------- tensor-core GEMM body: compensated bf16 (3-MMA), fp32 accum ----------------
// C[M x 64] = A[M x K] @ W[K x 64]; 128x64 block tile, 8 warps (m16 each), double-buffered.
// A stored [row][k] bf16 (stride 24 halves = 48B), W stored [n][k] bf16 (stride 24).
// smem: Wbig[2][64][24] @0 (6144B), Wres @6144, Abig[2][128][24] @12288 (12288B), Ares @24576.
// Total 36864B.
typedef __nv_bfloat16 bfx;
__device__ __forceinline__ void gemm_body(
    int gb, char* sh,
    const float* __restrict__ A1, const float* __restrict__ W1, const float* __restrict__ b1,
    float* __restrict__ C1, __half2* __restrict__ H1, int M1,
    const float* __restrict__ A2, const float* __restrict__ W2, const float* __restrict__ b2,
    float* __restrict__ C2, __half2* __restrict__ H2, int M2,
    int K, int doRelu, int nb1)
{
    bfx (*Wbig)[64][24]  = (bfx(*)[64][24])sh;
    bfx (*Wres)[64][24]  = (bfx(*)[64][24])(sh + 6144);
    bfx (*Abig)[128][24] = (bfx(*)[128][24])(sh + 12288);
    bfx (*Ares)[128][24] = (bfx(*)[128][24])(sh + 24576);

    const float* A; const float* W; const float* bias; float* C; __half2* halfC; int M, bm0;
    if (gb < nb1) {
        A = A1; W = W1; bias = b1; C = C1; halfC = H1; M = M1; bm0 = gb * 128;
    } else {
        A = A2; W = W2; bias = b2; C = C2; halfC = H2; M = M2; bm0 = (gb - nb1) * 128;
    }

    int t = threadIdx.x;
    int wk = t >> 4;          // W-tile k row (0..15)
    int wc = t & 15;          // W-tile col quad (cols wc*4..wc*4+3)
    int lrow = t >> 1;        // A-tile row (0..127)
    int lq = (t & 1) * 8;     // A-tile k offset (0 or 8)
    int row = bm0 + lrow;
    bool rv = row < M;
    const float* Arow = A + (size_t)row * K;

    float4 p0 = make_float4(0.f, 0.f, 0.f, 0.f), p1 = p0, wv = p0;

#define FETCHA(k0) do { \
    if (rv) { p0 = *(const float4*)(Arow + (k0) + lq); p1 = *(const float4*)(Arow + (k0) + lq + 4); } \
} while (0)
#define FETCHW(k0) do { wv = *(const float4*)(W + (size_t)((k0) + wk) * 64 + wc * 4); } while (0)
#define SPLITA(buf, kk, x) do { \
    bfx hb_ = __float2bfloat16_rn(x); \
    Abig[buf][lrow][kk] = hb_; \
    Ares[buf][lrow][kk] = __float2bfloat16_rn((x) - __bfloat162float(hb_)); \
} while (0)
#define STAGEA(buf) do { \
    SPLITA(buf, lq + 0, p0.x); SPLITA(buf, lq + 1, p0.y); \
    SPLITA(buf, lq + 2, p0.z); SPLITA(buf, lq + 3, p0.w); \
    SPLITA(buf, lq + 4, p1.x); SPLITA(buf, lq + 5, p1.y); \
    SPLITA(buf, lq + 6, p1.z); SPLITA(buf, lq + 7, p1.w); \
} while (0)
#define SPLITW(buf, nn, x) do { \
    bfx hb_ = __float2bfloat16_rn(x); \
    Wbig[buf][nn][wk] = hb_; \
    Wres[buf][nn][wk] = __float2bfloat16_rn((x) - __bfloat162float(hb_)); \
} while (0)
#define STAGEW(buf) do { \
    SPLITW(buf, wc * 4 + 0, wv.x); SPLITW(buf, wc * 4 + 1, wv.y); \
    SPLITW(buf, wc * 4 + 2, wv.z); SPLITW(buf, wc * 4 + 3, wv.w); \
} while (0)

    FETCHA(0); FETCHW(0);
    STAGEA(0); STAGEW(0);
    __syncthreads();

    float acc[8][4];
#pragma unroll
    for (int i = 0; i < 8; i++)
#pragma unroll
        for (int j = 0; j < 4; j++) acc[i][j] = 0.f;

    int warp = t >> 5, lane = t & 31;
    int gid = lane >> 2;      // 0..7
    int tig = lane & 3;       // 0..3
    int warpRow = warp * 16;
    int nt = K >> 4;

    for (int tile = 0; tile < nt; tile++) {
        int buf = tile & 1;
        if (tile + 1 < nt) { FETCHA((tile + 1) << 4); FETCHW((tile + 1) << 4); }

        // A frags (m16n8k16: a0 row g k[2t,2t+1], a1 row g+8, a2 row g k[2t+8,2t+9], a3 row g+8)
        unsigned a0 = *(const unsigned*)&Abig[buf][warpRow + gid    ][2 * tig];
        unsigned a1 = *(const unsigned*)&Abig[buf][warpRow + gid + 8][2 * tig];
        unsigned a2 = *(const unsigned*)&Abig[buf][warpRow + gid    ][2 * tig + 8];
        unsigned a3 = *(const unsigned*)&Abig[buf][warpRow + gid + 8][2 * tig + 8];
        unsigned r0 = *(const unsigned*)&Ares[buf][warpRow + gid    ][2 * tig];
        unsigned r1 = *(const unsigned*)&Ares[buf][warpRow + gid + 8][2 * tig];
        unsigned r2 = *(const unsigned*)&Ares[buf][warpRow + gid    ][2 * tig + 8];
        unsigned r3 = *(const unsigned*)&Ares[buf][warpRow + gid + 8][2 * tig + 8];

#pragma unroll
        for (int n = 0; n < 8; n++) {
            unsigned b0 = *(const unsigned*)&Wbig[buf][n * 8 + gid][2 * tig];
            unsigned b1 = *(const unsigned*)&Wbig[buf][n * 8 + gid][2 * tig + 8];
            unsigned c0 = *(const unsigned*)&Wres[buf][n * 8 + gid][2 * tig];
            unsigned c1 = *(const unsigned*)&Wres[buf][n * 8 + gid][2 * tig + 8];
            mma_bf16(acc[n], a0, a1, a2, a3, b0, b1);   // big*big
            mma_bf16(acc[n], r0, r1, r2, r3, b0, b1);   // resA*big
            mma_bf16(acc[n], a0, a1, a2, a3, c0, c1);   // big*resB
        }

        if (tile + 1 < nt) {
            __syncthreads();
            STAGEA((tile + 1) & 1);
            STAGEW((tile + 1) & 1);
            __syncthreads();
        }
    }

    // epilogue: c0/c1 -> row warpRow+gid, cols 2*tig,2*tig+1 of each n-tile; c2/c3 -> row+8
    int er0 = bm0 + warpRow + gid;
    int er1 = er0 + 8;
#pragma unroll
    for (int n = 0; n < 8; n++) {
        int col = n * 8 + 2 * tig;
        float bx = 0.f, by = 0.f;
        if (bias) { float2 bb = *(const float2*)(bias + col); bx = bb.x; by = bb.y; }
        float v0 = acc[n][0] + bx, v1 = acc[n][1] + by;
        float v2 = acc[n][2] + bx, v3 = acc[n][3] + by;
        if (doRelu) {
            v0 = fmaxf(v0, 0.f); v1 = fmaxf(v1, 0.f);
            v2 = fmaxf(v2, 0.f); v3 = fmaxf(v3, 0.f);
        }
        if (er0 < M) {
            *(float2*)(C + (size_t)er0 * 64 + col) = make_float2(v0, v1);
            if (halfC) halfC[(size_t)er0 * 32 + col / 2] = __floats2half2_rn(v0, v1);
        }
        if (er1 < M) {
            *(float2*)(C + (size_t)er1 * 64 + col) = make_float2(v2, v3);
            if (halfC) halfC[(size_t)er1 * 32 + col / 2] = __floats2half2_rn(v2, v3);
        }
    }
#undef FETCHA
#undef FETCHW
#undef SPLITA
#undef STAGEA
#undef SPLITW
#undef STAGEW
}

// ---------------- fused edge-stage + GEMM-chunk co-kernel ----------------
// stage 1 = degree count; stage 5 = CSR fill writing (src, onorm[src]) pairs
__global__ void __launch_bounds__(256, 3) csr_gemm_kernel(
    int stage, int nGemm, int gemmStart,
    const int* __restrict__ esrc, const int* __restrict__ edst,
    const float* __restrict__ A1, const float* __restrict__ W1, const float* __restrict__ b1,
    float* __restrict__ C1, __half2* __restrict__ H1, int M1,
    const float* __restrict__ A2, const float* __restrict__ W2, const float* __restrict__ b2,
    float* __restrict__ C2, __half2* __restrict__ H2, int M2,
    int K, int doRelu, int nb1, int nbTot)
{
    __shared__ char sh[36864];
    int tid = threadIdx.x;

    if ((int)blockIdx.x < nGemm) {
        int gb = gemmStart + blockIdx.x;
        if (gb < nbTot)
            gemm_body(gb, sh, A1, W1, b1, C1, H1, M1, A2, W2, b2, C2, H2, M2, K, doRelu, nb1);
        return;
    }
    int cb = blockIdx.x - nGemm;
    int base = (cb * 256 + tid) * 4;
    if (base >= NE) return;

    int4 s4 = *(const int4*)(esrc + base);
    int4 d4 = *(const int4*)(edst + base);
    if (stage == 1) {
        atomicAdd(&g_ocnt[s4.x], 1); atomicAdd(&g_icnt[d4.x], 1);
        atomicAdd(&g_ocnt[s4.y], 1); atomicAdd(&g_icnt[d4.y], 1);
        atomicAdd(&g_ocnt[s4.z], 1); atomicAdd(&g_icnt[d4.z], 1);
        atomicAdd(&g_ocnt[s4.w], 1); atomicAdd(&g_icnt[d4.w], 1);
    } else {
        float wx = g_onorm[s4.x], wy = g_onorm[s4.y];
        float wz = g_onorm[s4.z], ww = g_onorm[s4.w];
        g_cpair[atomicAdd(&g_cur[d4.x], 1)] = make_float2(__int_as_float(s4.x), wx);
        g_cpair[atomicAdd(&g_cur[d4.y], 1)] = make_float2(__int_as_float(s4.y), wy);
        g_cpair[atomicAdd(&g_cur[d4.z], 1)] = make_float2(__int_as_float(s4.z), wz);
        g_cpair[atomicAdd(&g_cur[d4.w], 1)] = make_float2(__int_as_float(s4.w), ww);
    }
}

// ---------------- standalone small kernels ----------------
__global__ void clear_kernel() {
    int i = blockIdx.x * blockDim.x + threadIdx.x;
    if (i < NN) { g_ocnt[i] = 0; g_icnt[i] = 0; }
}

__global__ void scan1_kernel() {
    __shared__ int wsum[8];
    int tid = threadIdx.x;
    int base = blockIdx.x * 1024 + tid * 4;
    int v0 = (base + 0 < NN) ? g_icnt[base + 0] : 0;
    int v1 = (base + 1 < NN) ? g_icnt[base + 1] : 0;
    int v2 = (base + 2 < NN) ? g_icnt[base + 2] : 0;
    int v3 = (base + 3 < NN) ? g_icnt[base + 3] : 0;
    int s1 = v0, s2 = v0 + v1, s3 = v0 + v1 + v2, s = s3 + v3;
    int lane = tid & 31, wp = tid >> 5;
    int incl = s;
#pragma unroll
    for (int o = 1; o < 32; o <<= 1) {
        int n = __shfl_up_sync(0xffffffffu, incl, o);
        if (lane >= o) incl += n;
    }
    if (lane == 31) wsum[wp] = incl;
    __syncthreads();
    int wbase = 0;
    for (int k = 0; k < wp; k++) wbase += wsum[k];
    int et = wbase + incl - s;
    if (base + 0 < NN) g_off[base + 0] = et;
    if (base + 1 < NN) g_off[base + 1] = et + s1;
    if (base + 2 < NN) g_off[base + 2] = et + s2;
    if (base + 3 < NN) g_off[base + 3] = et + s3;
    if (tid == 255) g_bsum[blockIdx.x] = wbase + incl;
}

__global__ void scan3_kernel() {
    __shared__ int sboff[SCAN_NBLK];
    __shared__ int wsum[4];
    int tid = threadIdx.x;
    if (tid < 128) {
        int v = (tid < SCAN_NBLK) ? g_bsum[tid] : 0;
        int lane = tid & 31, wp = tid >> 5;
        int incl = v;
#pragma unroll
        for (int o = 1; o < 32; o <<= 1) {
            int n = __shfl_up_sync(0xffffffffu, incl, o);
            if (lane >= o) incl += n;
        }
        if (lane == 31) wsum[wp] = incl;
        __syncthreads();
        int wbase = 0;
        for (int k = 0; k < wp; k++) wbase += wsum[k];
        if (tid < SCAN_NBLK) sboff[tid] = wbase + incl - v;
    } else {
        __syncthreads();
    }
    __syncthreads();
    int i = blockIdx.x * blockDim.x + tid;
    if (i < NN) {
        int o = g_off[i] + sboff[i >> 10];
        g_off[i] = o;
        g_cur[i] = o;
        float od = fmaxf((float)g_ocnt[i], 1.0f);
        g_onorm[i]  = rsqrtf(od);
        g_rodeg[i]  = sqrtf(od);
        g_innorm[i] = rsqrtf(fmaxf((float)g_icnt[i], 1.0f));
    }
}

// ---------------- plain dual GEMM ----------------
__global__ void __launch_bounds__(256, 3) gemm_dual(
    const float* __restrict__ A1, const float* __restrict__ W1, const float* __restrict__ b1,
    float* __restrict__ C1, int M1,
    const float* __restrict__ A2, const float* __restrict__ W2, const float* __restrict__ b2,
    float* __restrict__ C2, int M2,
    int K, int doRelu, int nb1)
{
    __shared__ char sh[36864];
    gemm_body(blockIdx.x, sh, A1, W1, b1, C1, nullptr, M1, A2, W2, b2, C2, nullptr, M2, K, doRelu, nb1);
}

// ---------------- GCN layer 1: warp/node, fp16 neighbor rows, paired CSR ----------------
__global__ void gather1_kernel() {
    int gw = (blockIdx.x * blockDim.x + threadIdx.x) >> 5;
    int lane = threadIdx.x & 31;
    if (gw >= NN) return;
    int start = g_off[gw];
    int deg = g_icnt[gw];
    float a0 = 0.f, a1 = 0.f;
    int nfull = deg & ~31;
    for (int j0 = 0; j0 < nfull; j0 += 32) {
        float2 pr = g_cpair[start + j0 + lane];
        int idx = __float_as_int(pr.x);
        float w = pr.y;
#pragma unroll
        for (int jj = 0; jj < 32; jj++) {
            int   s  = __shfl_sync(0xffffffffu, idx, jj);
            float wv = __shfl_sync(0xffffffffu, w, jj);
            float2 r = __half22float2(g_e0h[(size_t)s * 32 + lane]);
            a0 += wv * r.x;
            a1 += wv * r.y;
        }
    }
    int rem = deg - nfull;
    if (rem) {
        int idx = 0; float w = 0.f;
        if (lane < rem) {
            float2 pr = g_cpair[start + nfull + lane];
            idx = __float_as_int(pr.x);
            w = pr.y;
        }
        for (int jj = 0; jj < rem; jj++) {
            int   s  = __shfl_sync(0xffffffffu, idx, jj);
            float wv = __shfl_sync(0xffffffffu, w, jj);
            float2 r = __half22float2(g_e0h[(size_t)s * 32 + lane]);
            a0 += wv * r.x;
            a1 += wv * r.y;
        }
    }
    float sc = g_innorm[gw] * g_onorm[gw];
    float2 v = make_float2(a0 * sc, a1 * sc);
    *(float2*)(g_agg0s + (size_t)gw * 64 + 2 * lane) = v;
    g_agg0sh[(size_t)gw * 32 + lane] = __floats2half2_rn(v.x, v.y);
}

// ---------------- GCN layer 2 + final combine (fp16 neighbor rows) ----------------
__global__ void gather2_final_kernel(const float* __restrict__ side, float* __restrict__ out) {
    int gw = (blockIdx.x * blockDim.x + threadIdx.x) >> 5;
    int lane = threadIdx.x & 31;
    if (gw >= NN) return;
    int start = g_off[gw];
    int deg = g_icnt[gw];
    float a0 = 0.f, a1 = 0.f;
    int nfull = deg & ~31;
    for (int j0 = 0; j0 < nfull; j0 += 32) {
        int idx = __float_as_int(g_cpair[start + j0 + lane].x);
#pragma unroll
        for (int jj = 0; jj < 32; jj++) {
            int s = __shfl_sync(0xffffffffu, idx, jj);
            float2 r = __half22float2(g_agg0sh[(size_t)s * 32 + lane]);
            a0 += r.x;
            a1 += r.y;
        }
    }
    int rem = deg - nfull;
    if (rem) {
        int idx = 0;
        if (lane < rem) idx = __float_as_int(g_cpair[start + nfull + lane].x);
        for (int jj = 0; jj < rem; jj++) {
            int s = __shfl_sync(0xffffffffu, idx, jj);
            float2 r = __half22float2(g_agg0sh[(size_t)s * 32 + lane]);
            a0 += r.x;
            a1 += r.y;
        }
    }
    float inn3 = g_innorm[gw] * (1.0f / 3.0f);
    float half_rodeg = 0.5f * g_rodeg[gw];
    size_t base = (size_t)gw * 64 + 2 * lane;
    float2 e = *(const float2*)(g_e0 + base);
    float2 m = *(const float2*)(g_agg0s + base);
    float r0v = e.x + half_rodeg * m.x + inn3 * a0;
    float r1v = e.y + half_rodeg * m.y + inn3 * a1;
    if (gw >= NU) {
        float2 sd = *(const float2*)(side + (size_t)(gw - NU) * 64 + 2 * lane);
        r0v += sd.x;
        r1v += sd.y;
    }
    *(float2*)(out + base) = make_float2(r0v, r1v);
}

// ---------------- decode epilogue (float2 gathers) ----------------
__global__ void decode_kernel(const float* __restrict__ Tf, const float* __restrict__ Tcf,
                              const float* __restrict__ W1, const float* __restrict__ W2,
                              const int* __restrict__ userId, const int* __restrict__ posId,
                              const int* __restrict__ negId,
                              float* __restrict__ of, float* __restrict__ ocf) {
    __shared__ float w2s[64];
    __shared__ float w1l[64];
    int t = threadIdx.x;
    if (t < 64) {
        w2s[t] = W2[t];
        w1l[t] = W1[128 * 64 + t];
    }
    __syncthreads();

    int warp = t >> 5, lane = t & 31;
    int pair = blockIdx.x * 8 + warp;
    if (pair >= NP) return;

    int u  = userId[pair];
    int p  = posId[pair];
    int ng = negId[pair];

    float2 uv = *(const float2*)(g_xu + (size_t)u * 64 + 2 * lane);
    float2 pv = *(const float2*)(g_xi + (size_t)p * 64 + 2 * lane);
    float2 nv = *(const float2*)(g_xi + (size_t)ng * 64 + 2 * lane);
    float2 wl = *(const float2*)(w1l + 2 * lane);
    float2 w2 = *(const float2*)(w2s + 2 * lane);

    float tfp = Tf[pair],  tfn = Tf[pair + NP];
    float tcp = Tcf[pair], tcn = Tcf[pair + NP];

    auto combo = [&](float j0, float j1, float T) -> float {
        float x0 = uv.x + j0 + T * wl.x;
        float x1 = uv.y + j1 + T * wl.y;
        float e0 = x0 > 0.f ? x0 : (expf(x0) - 1.0f);
        float e1 = x1 > 0.f ? x1 : (expf(x1) - 1.0f);
        float s = e0 * w2.x + e1 * w2.y;
        s += __shfl_down_sync(0xffffffffu, s, 16);
        s += __shfl_down_sync(0xffffffffu, s, 8);
        s += __shfl_down_sync(0xffffffffu, s, 4);
        s += __shfl_down_sync(0xffffffffu, s, 2);
        s += __shfl_down_sync(0xffffffffu, s, 1);
        return s;
    };

    float rf_p = combo(pv.x, pv.y, tfp);
    float rf_n = combo(nv.x, nv.y, tfn);
    float rc_p = combo(pv.x, pv.y, tcp);
    float rc_n = combo(nv.x, nv.y, tcn);

    if (lane == 0) {
        of[pair]       = rf_p;
        of[pair + NP]  = rf_n;
        ocf[pair]      = rc_p;
        ocf[pair + NP] = rc_n;
    }
}

// ---------------- launch ----------------
extern "C" void kernel_launch(void* const* d_in, const int* in_sizes, int n_in,
                              void* d_out, int out_size) {
    const float* userF = (const float*)d_in[0];
    const float* itemF = (const float*)d_in[1];
    const float* side  = (const float*)d_in[2];
    const float* Tf    = (const float*)d_in[3];
    const float* Tcf   = (const float*)d_in[4];
    const float* Wu    = (const float*)d_in[5];
    const float* bu    = (const float*)d_in[6];
    const float* Wi    = (const float*)d_in[7];
    const float* bi    = (const float*)d_in[8];
    const float* W1    = (const float*)d_in[9];
    const float* b1    = (const float*)d_in[10];
    const float* W2    = (const float*)d_in[11];
    const int* esrc    = (const int*)d_in[12];
    const int* edst    = (const int*)d_in[13];
    const int* userId  = (const int*)d_in[14];
    const int* posId   = (const int*)d_in[15];
    const int* negId   = (const int*)d_in[16];

    float* out   = (float*)d_out;
    float* outI  = out + (size_t)NU * H;
    float* outLF = out + (size_t)NN * H;
    float* outLC = outLF + 2 * NP;

    float *pe0, *pxu, *pxi;
    __half2 *pe0h;
    cudaGetSymbolAddress((void**)&pe0, g_e0);
    cudaGetSymbolAddress((void**)&pe0h, g_e0h);
    cudaGetSymbolAddress((void**)&pxu, g_xu);
    cudaGetSymbolAddress((void**)&pxi, g_xi);

    int nb1 = (NU + 127) / 128;            // 391
    int nb2 = (NI + 127) / 128;            // 391
    int nbTot = nb1 + nb2;                 // 782
    int edgeBlocks = (NE / 4 + 255) / 256; // 1563

    clear_kernel<<<(NN + 255) / 256, 256>>>();

    // degree stage fused with first 300 GEMM blocks
    csr_gemm_kernel<<<300 + edgeBlocks, 256>>>(
        1, 300, 0, esrc, edst,
        userF, Wu, bu, pe0, pe0h, NU,
        itemF, Wi, bi, pe0 + (size_t)NU * H, pe0h + (size_t)NU * 32, NI,
        128, 1, nb1, nbTot);

    scan1_kernel<<<SCAN_NBLK, 256>>>();
    scan3_kernel<<<(NN + 255) / 256, 256>>>();

    // fill stage (writes (src, w) pairs) fused with remaining 482 GEMM blocks
    csr_gemm_kernel<<<482 + edgeBlocks, 256>>>(
        5, 482, 300, esrc, edst,
        userF, Wu, bu, pe0, pe0h, NU,
        itemF, Wi, bi, pe0 + (size_t)NU * H, pe0h + (size_t)NU * 32, NI,
        128, 1, nb1, nbTot);

    // GCN layers
    gather1_kernel<<<(NN * 32 + 255) / 256, 256>>>();
    gather2_final_kernel<<<(NN * 32 + 255) / 256, 256>>>(side, out);

    // per-node decode transforms
    gemm_dual<<<nbTot, 256>>>(out,  W1,           b1,      pxu, NU,
                              outI, W1 + 64 * 64, nullptr, pxi, NI,
                              64, 0, nb1);

    // decode epilogue
    decode_kernel<<<(NP + 7) / 8, 256>>>(Tf, Tcf, W1, W2, userId, posId, negId, outLF, outLC);
}

// round 14
// speedup vs baseline: 1.0911x; 1.0911x over previous
#include <cuda_runtime.h>
#include <cuda_fp16.h>
#include <math.h>

#define NU 50000
#define NI 50000
#define NN 100000
#define NE 1600000
#define NP 200000
#define H  64
#define SCAN_NBLK ((NN + 1023) / 1024)   // 98

// ---------------- device scratch ----------------
__device__ int   g_ocnt[NN];
__device__ int   g_icnt[NN];
__device__ float g_onorm[NN];
__device__ float g_innorm[NN];
__device__ float g_rodeg[NN];               // sqrt(max(out_deg,1))
__device__ int   g_off[NN];
__device__ int   g_cur[NN];
__device__ int   g_bsum[SCAN_NBLK];
__device__ float2 g_cpair[NE];              // (src as int bits, onorm[src])
__device__ float g_e0[(size_t)NN * H];
__device__ __half2 g_e0h[(size_t)NN * 32];      // fp16 mirror of e0 (gather reads)
__device__ float g_agg0s[(size_t)NN * H];   // layer-1 out, prescaled by onorm (fp32)
__device__ __half2 g_agg0sh[(size_t)NN * 32];   // fp16 mirror (gather reads)
__device__ float g_xu[(size_t)NU * H];
__device__ float g_xi[(size_t)NI * H];
__device__ __half2 g_xuh[(size_t)NU * 32];      // fp16 mirror of xu (decode reads)
__device__ __half2 g_xih[(size_t)NI * 32];      // fp16 mirror of xi (decode reads)

// ---------------- tf32 helpers ----------------
__device__ __forceinline__ float to_tf32(float x) {
    float r;
    asm("cvt.rna.tf32.f32 %0, %1;" : "=f"(r) : "f"(x));
    return r;
}

__device__ __forceinline__ void mma_tf32(float c[4],
                                         unsigned a0, unsigned a1, unsigned a2, unsigned a3,
                                         unsigned b0, unsigned b1) {
    asm volatile(
        "mma.sync.aligned.m16n8k8.row.col.f32.tf32.tf32.f32 "
        "{%0,%1,%2,%3},{%4,%5,%6,%7},{%8,%9},{%0,%1,%2,%3};"
        : "+f"(c[0]), "+f"(c[1]), "+f"(c[2]), "+f"(c[3])
        : "r"(a0), "r"(a1), "r"(a2), "r"(a3), "r"(b0), "r"(b1));
}

// ---------------- tensor-core GEMM body (tf32 mma, fp32 accum) ----------------
// C[M x 64] = A[M x K] @ W[K x 64]; 128x64 block tile, 8 warps (m16 each).
// sh layout: Ws[2][16][88] at 0 (11264B), As[2][16][136] at 11264 (17408B). Total 28672B.
#define WS_STRIDE 88
#define AS_STRIDE 136
__device__ __forceinline__ void gemm_body(
    int gb, char* sh,
    const float* __restrict__ A1, const float* __restrict__ W1, const float* __restrict__ b1,
    float* __restrict__ C1, __half2* __restrict__ H1, int M1,
    const float* __restrict__ A2, const float* __restrict__ W2, const float* __restrict__ b2,
    float* __restrict__ C2, __half2* __restrict__ H2, int M2,
    int K, int doRelu, int nb1)
{
    float (*Ws)[16][WS_STRIDE] = (float(*)[16][WS_STRIDE])sh;
    float (*As)[16][AS_STRIDE] = (float(*)[16][AS_STRIDE])(sh + 11264);

    const float* A; const float* W; const float* bias; float* C; __half2* halfC; int M, bm0;
    if (gb < nb1) {
        A = A1; W = W1; bias = b1; C = C1; halfC = H1; M = M1; bm0 = gb * 128;
    } else {
        A = A2; W = W2; bias = b2; C = C2; halfC = H2; M = M2; bm0 = (gb - nb1) * 128;
    }

    int t = threadIdx.x;
    int wk = t >> 4;          // W-tile k row (0..15)
    int wc = t & 15;          // W-tile col quad
    int lrow = t >> 1;        // A-tile row (0..127)
    int lq = (t & 1) * 8;     // A-tile k offset
    int row = bm0 + lrow;
    bool rv = row < M;
    const float* Ar = A + (size_t)row * K;

    float4 p0 = make_float4(0.f, 0.f, 0.f, 0.f), p1 = p0, wv = p0;

#define FETCHA(k0) do { \
    if (rv) { p0 = *(const float4*)(Ar + (k0) + lq); p1 = *(const float4*)(Ar + (k0) + lq + 4); } \
} while (0)
#define FETCHW(k0) do { wv = *(const float4*)(W + (size_t)((k0) + wk) * 64 + wc * 4); } while (0)
#define STAGEA(buf) do { \
    As[buf][lq + 0][lrow] = to_tf32(p0.x); As[buf][lq + 1][lrow] = to_tf32(p0.y); \
    As[buf][lq + 2][lrow] = to_tf32(p0.z); As[buf][lq + 3][lrow] = to_tf32(p0.w); \
    As[buf][lq + 4][lrow] = to_tf32(p1.x); As[buf][lq + 5][lrow] = to_tf32(p1.y); \
    As[buf][lq + 6][lrow] = to_tf32(p1.z); As[buf][lq + 7][lrow] = to_tf32(p1.w); \
} while (0)
#define STAGEW(buf) do { \
    Ws[buf][wk][wc * 4 + 0] = to_tf32(wv.x); Ws[buf][wk][wc * 4 + 1] = to_tf32(wv.y); \
    Ws[buf][wk][wc * 4 + 2] = to_tf32(wv.z); Ws[buf][wk][wc * 4 + 3] = to_tf32(wv.w); \
} while (0)

    FETCHA(0); FETCHW(0);
    STAGEA(0); STAGEW(0);
    __syncthreads();

    float acc[8][4];
#pragma unroll
    for (int i = 0; i < 8; i++)
#pragma unroll
        for (int j = 0; j < 4; j++) acc[i][j] = 0.f;

    int warp = t >> 5, lane = t & 31;
    int gid = lane >> 2;      // 0..7
    int tig = lane & 3;       // 0..3
    int warpRow = warp * 16;
    int nt = K >> 4;

    for (int tile = 0; tile < nt; tile++) {
        int buf = tile & 1;
        if (tile + 1 < nt) { FETCHA((tile + 1) << 4); FETCHW((tile + 1) << 4); }

#pragma unroll
        for (int ks = 0; ks < 16; ks += 8) {
            unsigned a0 = __float_as_uint(As[buf][ks + tig    ][warpRow + gid]);
            unsigned a1 = __float_as_uint(As[buf][ks + tig    ][warpRow + gid + 8]);
            unsigned a2 = __float_as_uint(As[buf][ks + tig + 4][warpRow + gid]);
            unsigned a3 = __float_as_uint(As[buf][ks + tig + 4][warpRow + gid + 8]);
#pragma unroll
            for (int n = 0; n < 8; n++) {
                unsigned b0 = __float_as_uint(Ws[buf][ks + tig    ][n * 8 + gid]);
                unsigned b1 = __float_as_uint(Ws[buf][ks + tig + 4][n * 8 + gid]);
                mma_tf32(acc[n], a0, a1, a2, a3, b0, b1);
            }
        }

        if (tile + 1 < nt) {
            __syncthreads();
            STAGEA((tile + 1) & 1);
            STAGEW((tile + 1) & 1);
            __syncthreads();
        }
    }

    // epilogue: c0/c1 -> row warpRow+gid, cols 2*tig,2*tig+1 of each n-tile; c2/c3 -> row+8
    int r0 = bm0 + warpRow + gid;
    int r1 = r0 + 8;
#pragma unroll
    for (int n = 0; n < 8; n++) {
        int col = n * 8 + 2 * tig;
        float bx = 0.f, by = 0.f;
        if (bias) { float2 bb = *(const float2*)(bias + col); bx = bb.x; by = bb.y; }
        float v0 = acc[n][0] + bx, v1 = acc[n][1] + by;
        float v2 = acc[n][2] + bx, v3 = acc[n][3] + by;
        if (doRelu) {
            v0 = fmaxf(v0, 0.f); v1 = fmaxf(v1, 0.f);
            v2 = fmaxf(v2, 0.f); v3 = fmaxf(v3, 0.f);
        }
        if (r0 < M) {
            *(float2*)(C + (size_t)r0 * 64 + col) = make_float2(v0, v1);
            if (halfC) halfC[(size_t)r0 * 32 + col / 2] = __floats2half2_rn(v0, v1);
        }
        if (r1 < M) {
            *(float2*)(C + (size_t)r1 * 64 + col) = make_float2(v2, v3);
            if (halfC) halfC[(size_t)r1 * 32 + col / 2] = __floats2half2_rn(v2, v3);
        }
    }
#undef FETCHA
#undef FETCHW
#undef STAGEA
#undef STAGEW
}

// ---------------- fused edge-stage + GEMM-chunk co-kernel ----------------
// stage 1 = degree count; stage 5 = CSR fill writing (src, onorm[src]) pairs
__global__ void __launch_bounds__(256, 3) csr_gemm_kernel(
    int stage, int nGemm, int gemmStart,
    const int* __restrict__ esrc, const int* __restrict__ edst,
    const float* __restrict__ A1, const float* __restrict__ W1, const float* __restrict__ b1,
    float* __restrict__ C1, __half2* __restrict__ H1, int M1,
    const float* __restrict__ A2, const float* __restrict__ W2, const float* __restrict__ b2,
    float* __restrict__ C2, __half2* __restrict__ H2, int M2,
    int K, int doRelu, int nb1, int nbTot)
{
    __shared__ char sh[28672];
    int tid = threadIdx.x;

    if ((int)blockIdx.x < nGemm) {
        int gb = gemmStart + blockIdx.x;
        if (gb < nbTot)
            gemm_body(gb, sh, A1, W1, b1, C1, H1, M1, A2, W2, b2, C2, H2, M2, K, doRelu, nb1);
        return;
    }
    int cb = blockIdx.x - nGemm;
    int base = (cb * 256 + tid) * 4;
    if (base >= NE) return;

    int4 s4 = *(const int4*)(esrc + base);
    int4 d4 = *(const int4*)(edst + base);
    if (stage == 1) {
        atomicAdd(&g_ocnt[s4.x], 1); atomicAdd(&g_icnt[d4.x], 1);
        atomicAdd(&g_ocnt[s4.y], 1); atomicAdd(&g_icnt[d4.y], 1);
        atomicAdd(&g_ocnt[s4.z], 1); atomicAdd(&g_icnt[d4.z], 1);
        atomicAdd(&g_ocnt[s4.w], 1); atomicAdd(&g_icnt[d4.w], 1);
    } else {
        float wx = g_onorm[s4.x], wy = g_onorm[s4.y];
        float wz = g_onorm[s4.z], ww = g_onorm[s4.w];
        g_cpair[atomicAdd(&g_cur[d4.x], 1)] = make_float2(__int_as_float(s4.x), wx);
        g_cpair[atomicAdd(&g_cur[d4.y], 1)] = make_float2(__int_as_float(s4.y), wy);
        g_cpair[atomicAdd(&g_cur[d4.z], 1)] = make_float2(__int_as_float(s4.z), wz);
        g_cpair[atomicAdd(&g_cur[d4.w], 1)] = make_float2(__int_as_float(s4.w), ww);
    }
}

// ---------------- standalone small kernels ----------------
__global__ void clear_kernel() {
    int i = blockIdx.x * blockDim.x + threadIdx.x;
    if (i < NN) { g_ocnt[i] = 0; g_icnt[i] = 0; }
}

__global__ void scan1_kernel() {
    __shared__ int wsum[8];
    int tid = threadIdx.x;
    int base = blockIdx.x * 1024 + tid * 4;
    int v0 = (base + 0 < NN) ? g_icnt[base + 0] : 0;
    int v1 = (base + 1 < NN) ? g_icnt[base + 1] : 0;
    int v2 = (base + 2 < NN) ? g_icnt[base + 2] : 0;
    int v3 = (base + 3 < NN) ? g_icnt[base + 3] : 0;
    int s1 = v0, s2 = v0 + v1, s3 = v0 + v1 + v2, s = s3 + v3;
    int lane = tid & 31, wp = tid >> 5;
    int incl = s;
#pragma unroll
    for (int o = 1; o < 32; o <<= 1) {
        int n = __shfl_up_sync(0xffffffffu, incl, o);
        if (lane >= o) incl += n;
    }
    if (lane == 31) wsum[wp] = incl;
    __syncthreads();
    int wbase = 0;
    for (int k = 0; k < wp; k++) wbase += wsum[k];
    int et = wbase + incl - s;
    if (base + 0 < NN) g_off[base + 0] = et;
    if (base + 1 < NN) g_off[base + 1] = et + s1;
    if (base + 2 < NN) g_off[base + 2] = et + s2;
    if (base + 3 < NN) g_off[base + 3] = et + s3;
    if (tid == 255) g_bsum[blockIdx.x] = wbase + incl;
}

__global__ void scan3_kernel() {
    __shared__ int sboff[SCAN_NBLK];
    __shared__ int wsum[4];
    int tid = threadIdx.x;
    if (tid < 128) {
        int v = (tid < SCAN_NBLK) ? g_bsum[tid] : 0;
        int lane = tid & 31, wp = tid >> 5;
        int incl = v;
#pragma unroll
        for (int o = 1; o < 32; o <<= 1) {
            int n = __shfl_up_sync(0xffffffffu, incl, o);
            if (lane >= o) incl += n;
        }
        if (lane == 31) wsum[wp] = incl;
        __syncthreads();
        int wbase = 0;
        for (int k = 0; k < wp; k++) wbase += wsum[k];
        if (tid < SCAN_NBLK) sboff[tid] = wbase + incl - v;
    } else {
        __syncthreads();
    }
    __syncthreads();
    int i = blockIdx.x * blockDim.x + tid;
    if (i < NN) {
        int o = g_off[i] + sboff[i >> 10];
        g_off[i] = o;
        g_cur[i] = o;
        float od = fmaxf((float)g_ocnt[i], 1.0f);
        g_onorm[i]  = rsqrtf(od);
        g_rodeg[i]  = sqrtf(od);
        g_innorm[i] = rsqrtf(fmaxf((float)g_icnt[i], 1.0f));
    }
}

// ---------------- plain dual GEMM (writes fp16 mirrors for decode) ----------------
__global__ void __launch_bounds__(256, 3) gemm_dual(
    const float* __restrict__ A1, const float* __restrict__ W1, const float* __restrict__ b1,
    float* __restrict__ C1, __half2* __restrict__ H1, int M1,
    const float* __restrict__ A2, const float* __restrict__ W2, const float* __restrict__ b2,
    float* __restrict__ C2, __half2* __restrict__ H2, int M2,
    int K, int doRelu, int nb1)
{
    __shared__ char sh[28672];
    gemm_body(blockIdx.x, sh, A1, W1, b1, C1, H1, M1, A2, W2, b2, C2, H2, M2, K, doRelu, nb1);
}

// ---------------- GCN layer 1: warp/node, fp16 neighbor rows, paired CSR ----------------
__global__ void gather1_kernel() {
    int gw = (blockIdx.x * blockDim.x + threadIdx.x) >> 5;
    int lane = threadIdx.x & 31;
    if (gw >= NN) return;
    int start = g_off[gw];
    int deg = g_icnt[gw];
    float a0 = 0.f, a1 = 0.f;
    int nfull = deg & ~31;
    for (int j0 = 0; j0 < nfull; j0 += 32) {
        float2 pr = g_cpair[start + j0 + lane];
        int idx = __float_as_int(pr.x);
        float w = pr.y;
#pragma unroll
        for (int jj = 0; jj < 32; jj++) {
            int   s  = __shfl_sync(0xffffffffu, idx, jj);
            float wv = __shfl_sync(0xffffffffu, w, jj);
            float2 r = __half22float2(g_e0h[(size_t)s * 32 + lane]);
            a0 += wv * r.x;
            a1 += wv * r.y;
        }
    }
    int rem = deg - nfull;
    if (rem) {
        int idx = 0; float w = 0.f;
        if (lane < rem) {
            float2 pr = g_cpair[start + nfull + lane];
            idx = __float_as_int(pr.x);
            w = pr.y;
        }
        for (int jj = 0; jj < rem; jj++) {
            int   s  = __shfl_sync(0xffffffffu, idx, jj);
            float wv = __shfl_sync(0xffffffffu, w, jj);
            float2 r = __half22float2(g_e0h[(size_t)s * 32 + lane]);
            a0 += wv * r.x;
            a1 += wv * r.y;
        }
    }
    float sc = g_innorm[gw] * g_onorm[gw];
    float2 v = make_float2(a0 * sc, a1 * sc);
    *(float2*)(g_agg0s + (size_t)gw * 64 + 2 * lane) = v;
    g_agg0sh[(size_t)gw * 32 + lane] = __floats2half2_rn(v.x, v.y);
}

// ---------------- GCN layer 2 + final combine (fp16 neighbor rows) ----------------
__global__ void gather2_final_kernel(const float* __restrict__ side, float* __restrict__ out) {
    int gw = (blockIdx.x * blockDim.x + threadIdx.x) >> 5;
    int lane = threadIdx.x & 31;
    if (gw >= NN) return;
    int start = g_off[gw];
    int deg = g_icnt[gw];
    float a0 = 0.f, a1 = 0.f;
    int nfull = deg & ~31;
    for (int j0 = 0; j0 < nfull; j0 += 32) {
        int idx = __float_as_int(g_cpair[start + j0 + lane].x);
#pragma unroll
        for (int jj = 0; jj < 32; jj++) {
            int s = __shfl_sync(0xffffffffu, idx, jj);
            float2 r = __half22float2(g_agg0sh[(size_t)s * 32 + lane]);
            a0 += r.x;
            a1 += r.y;
        }
    }
    int rem = deg - nfull;
    if (rem) {
        int idx = 0;
        if (lane < rem) idx = __float_as_int(g_cpair[start + nfull + lane].x);
        for (int jj = 0; jj < rem; jj++) {
            int s = __shfl_sync(0xffffffffu, idx, jj);
            float2 r = __half22float2(g_agg0sh[(size_t)s * 32 + lane]);
            a0 += r.x;
            a1 += r.y;
        }
    }
    float inn3 = g_innorm[gw] * (1.0f / 3.0f);
    float half_rodeg = 0.5f * g_rodeg[gw];
    size_t base = (size_t)gw * 64 + 2 * lane;
    float2 e = *(const float2*)(g_e0 + base);
    float2 m = *(const float2*)(g_agg0s + base);
    float r0v = e.x + half_rodeg * m.x + inn3 * a0;
    float r1v = e.y + half_rodeg * m.y + inn3 * a1;
    if (gw >= NU) {
        float2 sd = *(const float2*)(side + (size_t)(gw - NU) * 64 + 2 * lane);
        r0v += sd.x;
        r1v += sd.y;
    }
    *(float2*)(out + base) = make_float2(r0v, r1v);
}

// ---------------- decode epilogue (fp16 row gathers) ----------------
__global__ void decode_kernel(const float* __restrict__ Tf, const float* __restrict__ Tcf,
                              const float* __restrict__ W1, const float* __restrict__ W2,
                              const int* __restrict__ userId, const int* __restrict__ posId,
                              const int* __restrict__ negId,
                              float* __restrict__ of, float* __restrict__ ocf) {
    __shared__ float w2s[64];
    __shared__ float w1l[64];
    int t = threadIdx.x;
    if (t < 64) {
        w2s[t] = W2[t];
        w1l[t] = W1[128 * 64 + t];
    }
    __syncthreads();

    int warp = t >> 5, lane = t & 31;
    int pair = blockIdx.x * 8 + warp;
    if (pair >= NP) return;

    int u  = userId[pair];
    int p  = posId[pair];
    int ng = negId[pair];

    float2 uv = __half22float2(g_xuh[(size_t)u * 32 + lane]);
    float2 pv = __half22float2(g_xih[(size_t)p * 32 + lane]);
    float2 nv = __half22float2(g_xih[(size_t)ng * 32 + lane]);
    float2 wl = *(const float2*)(w1l + 2 * lane);
    float2 w2 = *(const float2*)(w2s + 2 * lane);

    float tfp = Tf[pair],  tfn = Tf[pair + NP];
    float tcp = Tcf[pair], tcn = Tcf[pair + NP];

    auto combo = [&](float j0, float j1, float T) -> float {
        float x0 = uv.x + j0 + T * wl.x;
        float x1 = uv.y + j1 + T * wl.y;
        float e0 = x0 > 0.f ? x0 : (expf(x0) - 1.0f);
        float e1 = x1 > 0.f ? x1 : (expf(x1) - 1.0f);
        float s = e0 * w2.x + e1 * w2.y;
        s += __shfl_down_sync(0xffffffffu, s, 16);
        s += __shfl_down_sync(0xffffffffu, s, 8);
        s += __shfl_down_sync(0xffffffffu, s, 4);
        s += __shfl_down_sync(0xffffffffu, s, 2);
        s += __shfl_down_sync(0xffffffffu, s, 1);
        return s;
    };

    float rf_p = combo(pv.x, pv.y, tfp);
    float rf_n = combo(nv.x, nv.y, tfn);
    float rc_p = combo(pv.x, pv.y, tcp);
    float rc_n = combo(nv.x, nv.y, tcn);

    if (lane == 0) {
        of[pair]       = rf_p;
        of[pair + NP]  = rf_n;
        ocf[pair]      = rc_p;
        ocf[pair + NP] = rc_n;
    }
}

// ---------------- launch ----------------
extern "C" void kernel_launch(void* const* d_in, const int* in_sizes, int n_in,
                              void* d_out, int out_size) {
    const float* userF = (const float*)d_in[0];
    const float* itemF = (const float*)d_in[1];
    const float* side  = (const float*)d_in[2];
    const float* Tf    = (const float*)d_in[3];
    const float* Tcf   = (const float*)d_in[4];
    const float* Wu    = (const float*)d_in[5];
    const float* bu    = (const float*)d_in[6];
    const float* Wi    = (const float*)d_in[7];
    const float* bi    = (const float*)d_in[8];
    const float* W1    = (const float*)d_in[9];
    const float* b1    = (const float*)d_in[10];
    const float* W2    = (const float*)d_in[11];
    const int* esrc    = (const int*)d_in[12];
    const int* edst    = (const int*)d_in[13];
    const int* userId  = (const int*)d_in[14];
    const int* posId   = (const int*)d_in[15];
    const int* negId   = (const int*)d_in[16];

    float* out   = (float*)d_out;
    float* outI  = out + (size_t)NU * H;
    float* outLF = out + (size_t)NN * H;
    float* outLC = outLF + 2 * NP;

    float *pe0, *pxu, *pxi;
    __half2 *pe0h, *pxuh, *pxih;
    cudaGetSymbolAddress((void**)&pe0, g_e0);
    cudaGetSymbolAddress((void**)&pe0h, g_e0h);
    cudaGetSymbolAddress((void**)&pxu, g_xu);
    cudaGetSymbolAddress((void**)&pxi, g_xi);
    cudaGetSymbolAddress((void**)&pxuh, g_xuh);
    cudaGetSymbolAddress((void**)&pxih, g_xih);

    int nb1 = (NU + 127) / 128;            // 391
    int nb2 = (NI + 127) / 128;            // 391
    int nbTot = nb1 + nb2;                 // 782
    int edgeBlocks = (NE / 4 + 255) / 256; // 1563

    clear_kernel<<<(NN + 255) / 256, 256>>>();

    // degree stage fused with first 300 GEMM blocks
    csr_gemm_kernel<<<300 + edgeBlocks, 256>>>(
        1, 300, 0, esrc, edst,
        userF, Wu, bu, pe0, pe0h, NU,
        itemF, Wi, bi, pe0 + (size_t)NU * H, pe0h + (size_t)NU * 32, NI,
        128, 1, nb1, nbTot);

    scan1_kernel<<<SCAN_NBLK, 256>>>();
    scan3_kernel<<<(NN + 255) / 256, 256>>>();

    // fill stage (writes (src, w) pairs) fused with remaining 482 GEMM blocks
    csr_gemm_kernel<<<482 + edgeBlocks, 256>>>(
        5, 482, 300, esrc, edst,
        userF, Wu, bu, pe0, pe0h, NU,
        itemF, Wi, bi, pe0 + (size_t)NU * H, pe0h + (size_t)NU * 32, NI,
        128, 1, nb1, nbTot);

    // GCN layers
    gather1_kernel<<<(NN * 32 + 255) / 256, 256>>>();
    gather2_final_kernel<<<(NN * 32 + 255) / 256, 256>>>(side, out);

    // per-node decode transforms (with fp16 mirrors for decode)
    gemm_dual<<<nbTot, 256>>>(out,  W1,           b1,      pxu, pxuh, NU,
                              outI, W1 + 64 * 64, nullptr, pxi, pxih, NI,
                              64, 0, nb1);

    // decode epilogue
    decode_kernel<<<(NP + 7) / 8, 256>>>(Tf, Tcf, W1, W2, userId, posId, negId, outLF, outLC);
}

// round 15
// speedup vs baseline: 1.1198x; 1.0263x over previous
#include <cuda_runtime.h>
#include <cuda_fp16.h>
#include <math.h>

#define NU 50000
#define NI 50000
#define NN 100000
#define NE 1600000
#define NP 200000
#define H  64
#define SCAN_NBLK ((NN + 1023) / 1024)   // 98

// ---------------- device scratch ----------------
__device__ int   g_ocnt[NN];
__device__ int   g_icnt[NN];
__device__ float g_onorm[NN];
__device__ float g_innorm[NN];
__device__ float g_rodeg[NN];               // sqrt(max(out_deg,1))
__device__ int   g_off[NN];
__device__ int   g_cur[NN];
__device__ int   g_bsum[SCAN_NBLK];
__device__ float2 g_cpair[NE];              // (src as int bits, onorm[src])
__device__ float g_e0[(size_t)NN * H];
__device__ __half2 g_e0h[(size_t)NN * 32];      // fp16 mirror of e0 (gather reads)
__device__ float g_agg0s[(size_t)NN * H];   // layer-1 out, prescaled by onorm (fp32)
__device__ __half2 g_agg0sh[(size_t)NN * 32];   // fp16 mirror (gather reads)
__device__ float g_xu[(size_t)NU * H];
__device__ float g_xi[(size_t)NI * H];

// ---------------- tf32 helpers ----------------
__device__ __forceinline__ float to_tf32(float x) {
    float r;
    asm("cvt.rna.tf32.f32 %0, %1;" : "=f"(r) : "f"(x));
    return r;
}

__device__ __forceinline__ void mma_tf32(float c[4],
                                         unsigned a0, unsigned a1, unsigned a2, unsigned a3,
                                         unsigned b0, unsigned b1) {
    asm volatile(
        "mma.sync.aligned.m16n8k8.row.col.f32.tf32.tf32.f32 "
        "{%0,%1,%2,%3},{%4,%5,%6,%7},{%8,%9},{%0,%1,%2,%3};"
        : "+f"(c[0]), "+f"(c[1]), "+f"(c[2]), "+f"(c[3])
        : "r"(a0), "r"(a1), "r"(a2), "r"(a3), "r"(b0), "r"(b1));
}

// ---------------- tensor-core GEMM body (tf32 mma, fp32 accum) ----------------
// C[M x 64] = A[M x K] @ W[K x 64]; 128x64 block tile, 8 warps (m16 each).
// sh layout: Ws[2][16][88] at 0 (11264B), As[2][16][136] at 11264 (17408B). Total 28672B.
#define WS_STRIDE 88
#define AS_STRIDE 136
__device__ __forceinline__ void gemm_body(
    int gb, char* sh,
    const float* __restrict__ A1, const float* __restrict__ W1, const float* __restrict__ b1,
    float* __restrict__ C1, __half2* __restrict__ H1, int M1,
    const float* __restrict__ A2, const float* __restrict__ W2, const float* __restrict__ b2,
    float* __restrict__ C2, __half2* __restrict__ H2, int M2,
    int K, int doRelu, int nb1)
{
    float (*Ws)[16][WS_STRIDE] = (float(*)[16][WS_STRIDE])sh;
    float (*As)[16][AS_STRIDE] = (float(*)[16][AS_STRIDE])(sh + 11264);

    const float* A; const float* W; const float* bias; float* C; __half2* halfC; int M, bm0;
    if (gb < nb1) {
        A = A1; W = W1; bias = b1; C = C1; halfC = H1; M = M1; bm0 = gb * 128;
    } else {
        A = A2; W = W2; bias = b2; C = C2; halfC = H2; M = M2; bm0 = (gb - nb1) * 128;
    }

    int t = threadIdx.x;
    int wk = t >> 4;          // W-tile k row (0..15)
    int wc = t & 15;          // W-tile col quad
    int lrow = t >> 1;        // A-tile row (0..127)
    int lq = (t & 1) * 8;     // A-tile k offset
    int row = bm0 + lrow;
    bool rv = row < M;
    const float* Ar = A + (size_t)row * K;

    float4 p0 = make_float4(0.f, 0.f, 0.f, 0.f), p1 = p0, wv = p0;

#define FETCHA(k0) do { \
    if (rv) { p0 = *(const float4*)(Ar + (k0) + lq); p1 = *(const float4*)(Ar + (k0) + lq + 4); } \
} while (0)
#define FETCHW(k0) do { wv = *(const float4*)(W + (size_t)((k0) + wk) * 64 + wc * 4); } while (0)
#define STAGEA(buf) do { \
    As[buf][lq + 0][lrow] = to_tf32(p0.x); As[buf][lq + 1][lrow] = to_tf32(p0.y); \
    As[buf][lq + 2][lrow] = to_tf32(p0.z); As[buf][lq + 3][lrow] = to_tf32(p0.w); \
    As[buf][lq + 4][lrow] = to_tf32(p1.x); As[buf][lq + 5][lrow] = to_tf32(p1.y); \
    As[buf][lq + 6][lrow] = to_tf32(p1.z); As[buf][lq + 7][lrow] = to_tf32(p1.w); \
} while (0)
#define STAGEW(buf) do { \
    Ws[buf][wk][wc * 4 + 0] = to_tf32(wv.x); Ws[buf][wk][wc * 4 + 1] = to_tf32(wv.y); \
    Ws[buf][wk][wc * 4 + 2] = to_tf32(wv.z); Ws[buf][wk][wc * 4 + 3] = to_tf32(wv.w); \
} while (0)

    FETCHA(0); FETCHW(0);
    STAGEA(0); STAGEW(0);
    __syncthreads();

    float acc[8][4];
#pragma unroll
    for (int i = 0; i < 8; i++)
#pragma unroll
        for (int j = 0; j < 4; j++) acc[i][j] = 0.f;

    int warp = t >> 5, lane = t & 31;
    int gid = lane >> 2;      // 0..7
    int tig = lane & 3;       // 0..3
    int warpRow = warp * 16;
    int nt = K >> 4;

    for (int tile = 0; tile < nt; tile++) {
        int buf = tile & 1;
        if (tile + 1 < nt) { FETCHA((tile + 1) << 4); FETCHW((tile + 1) << 4); }

#pragma unroll
        for (int ks = 0; ks < 16; ks += 8) {
            unsigned a0 = __float_as_uint(As[buf][ks + tig    ][warpRow + gid]);
            unsigned a1 = __float_as_uint(As[buf][ks + tig    ][warpRow + gid + 8]);
            unsigned a2 = __float_as_uint(As[buf][ks + tig + 4][warpRow + gid]);
            unsigned a3 = __float_as_uint(As[buf][ks + tig + 4][warpRow + gid + 8]);
#pragma unroll
            for (int n = 0; n < 8; n++) {
                unsigned b0 = __float_as_uint(Ws[buf][ks + tig    ][n * 8 + gid]);
                unsigned b1 = __float_as_uint(Ws[buf][ks + tig + 4][n * 8 + gid]);
                mma_tf32(acc[n], a0, a1, a2, a3, b0, b1);
            }
        }

        if (tile + 1 < nt) {
            __syncthreads();
            STAGEA((tile + 1) & 1);
            STAGEW((tile + 1) & 1);
            __syncthreads();
        }
    }

    // epilogue: c0/c1 -> row warpRow+gid, cols 2*tig,2*tig+1 of each n-tile; c2/c3 -> row+8
    int r0 = bm0 + warpRow + gid;
    int r1 = r0 + 8;
#pragma unroll
    for (int n = 0; n < 8; n++) {
        int col = n * 8 + 2 * tig;
        float bx = 0.f, by = 0.f;
        if (bias) { float2 bb = *(const float2*)(bias + col); bx = bb.x; by = bb.y; }
        float v0 = acc[n][0] + bx, v1 = acc[n][1] + by;
        float v2 = acc[n][2] + bx, v3 = acc[n][3] + by;
        if (doRelu) {
            v0 = fmaxf(v0, 0.f); v1 = fmaxf(v1, 0.f);
            v2 = fmaxf(v2, 0.f); v3 = fmaxf(v3, 0.f);
        }
        if (r0 < M) {
            *(float2*)(C + (size_t)r0 * 64 + col) = make_float2(v0, v1);
            if (halfC) halfC[(size_t)r0 * 32 + col / 2] = __floats2half2_rn(v0, v1);
        }
        if (r1 < M) {
            *(float2*)(C + (size_t)r1 * 64 + col) = make_float2(v2, v3);
            if (halfC) halfC[(size_t)r1 * 32 + col / 2] = __floats2half2_rn(v2, v3);
        }
    }
#undef FETCHA
#undef FETCHW
#undef STAGEA
#undef STAGEW
}

// ---------------- fused edge-stage + GEMM-chunk co-kernel ----------------
// stage 1 = degree count; stage 5 = CSR fill writing (src, onorm[src]) pairs
__global__ void __launch_bounds__(256, 3) csr_gemm_kernel(
    int stage, int nGemm, int gemmStart,
    const int* __restrict__ esrc, const int* __restrict__ edst,
    const float* __restrict__ A1, const float* __restrict__ W1, const float* __restrict__ b1,
    float* __restrict__ C1, __half2* __restrict__ H1, int M1,
    const float* __restrict__ A2, const float* __restrict__ W2, const float* __restrict__ b2,
    float* __restrict__ C2, __half2* __restrict__ H2, int M2,
    int K, int doRelu, int nb1, int nbTot)
{
    __shared__ char sh[28672];
    int tid = threadIdx.x;

    if ((int)blockIdx.x < nGemm) {
        int gb = gemmStart + blockIdx.x;
        if (gb < nbTot)
            gemm_body(gb, sh, A1, W1, b1, C1, H1, M1, A2, W2, b2, C2, H2, M2, K, doRelu, nb1);
        return;
    }
    int cb = blockIdx.x - nGemm;
    int base = (cb * 256 + tid) * 4;
    if (base >= NE) return;

    int4 s4 = *(const int4*)(esrc + base);
    int4 d4 = *(const int4*)(edst + base);
    if (stage == 1) {
        atomicAdd(&g_ocnt[s4.x], 1); atomicAdd(&g_icnt[d4.x], 1);
        atomicAdd(&g_ocnt[s4.y], 1); atomicAdd(&g_icnt[d4.y], 1);
        atomicAdd(&g_ocnt[s4.z], 1); atomicAdd(&g_icnt[d4.z], 1);
        atomicAdd(&g_ocnt[s4.w], 1); atomicAdd(&g_icnt[d4.w], 1);
    } else {
        float wx = g_onorm[s4.x], wy = g_onorm[s4.y];
        float wz = g_onorm[s4.z], ww = g_onorm[s4.w];
        g_cpair[atomicAdd(&g_cur[d4.x], 1)] = make_float2(__int_as_float(s4.x), wx);
        g_cpair[atomicAdd(&g_cur[d4.y], 1)] = make_float2(__int_as_float(s4.y), wy);
        g_cpair[atomicAdd(&g_cur[d4.z], 1)] = make_float2(__int_as_float(s4.z), wz);
        g_cpair[atomicAdd(&g_cur[d4.w], 1)] = make_float2(__int_as_float(s4.w), ww);
    }
}

// ---------------- standalone small kernels ----------------
__global__ void clear_kernel() {
    int i = blockIdx.x * blockDim.x + threadIdx.x;
    if (i < NN) { g_ocnt[i] = 0; g_icnt[i] = 0; }
}

__global__ void scan1_kernel() {
    __shared__ int wsum[8];
    int tid = threadIdx.x;
    int base = blockIdx.x * 1024 + tid * 4;
    int v0 = (base + 0 < NN) ? g_icnt[base + 0] : 0;
    int v1 = (base + 1 < NN) ? g_icnt[base + 1] : 0;
    int v2 = (base + 2 < NN) ? g_icnt[base + 2] : 0;
    int v3 = (base + 3 < NN) ? g_icnt[base + 3] : 0;
    int s1 = v0, s2 = v0 + v1, s3 = v0 + v1 + v2, s = s3 + v3;
    int lane = tid & 31, wp = tid >> 5;
    int incl = s;
#pragma unroll
    for (int o = 1; o < 32; o <<= 1) {
        int n = __shfl_up_sync(0xffffffffu, incl, o);
        if (lane >= o) incl += n;
    }
    if (lane == 31) wsum[wp] = incl;
    __syncthreads();
    int wbase = 0;
    for (int k = 0; k < wp; k++) wbase += wsum[k];
    int et = wbase + incl - s;
    if (base + 0 < NN) g_off[base + 0] = et;
    if (base + 1 < NN) g_off[base + 1] = et + s1;
    if (base + 2 < NN) g_off[base + 2] = et + s2;
    if (base + 3 < NN) g_off[base + 3] = et + s3;
    if (tid == 255) g_bsum[blockIdx.x] = wbase + incl;
}

__global__ void scan3_kernel() {
    __shared__ int sboff[SCAN_NBLK];
    __shared__ int wsum[4];
    int tid = threadIdx.x;
    if (tid < 128) {
        int v = (tid < SCAN_NBLK) ? g_bsum[tid] : 0;
        int lane = tid & 31, wp = tid >> 5;
        int incl = v;
#pragma unroll
        for (int o = 1; o < 32; o <<= 1) {
            int n = __shfl_up_sync(0xffffffffu, incl, o);
            if (lane >= o) incl += n;
        }
        if (lane == 31) wsum[wp] = incl;
        __syncthreads();
        int wbase = 0;
        for (int k = 0; k < wp; k++) wbase += wsum[k];
        if (tid < SCAN_NBLK) sboff[tid] = wbase + incl - v;
    } else {
        __syncthreads();
    }
    __syncthreads();
    int i = blockIdx.x * blockDim.x + tid;
    if (i < NN) {
        int o = g_off[i] + sboff[i >> 10];
        g_off[i] = o;
        g_cur[i] = o;
        float od = fmaxf((float)g_ocnt[i], 1.0f);
        g_onorm[i]  = rsqrtf(od);
        g_rodeg[i]  = sqrtf(od);
        g_innorm[i] = rsqrtf(fmaxf((float)g_icnt[i], 1.0f));
    }
}

// ---------------- plain dual GEMM ----------------
__global__ void __launch_bounds__(256, 3) gemm_dual(
    const float* __restrict__ A1, const float* __restrict__ W1, const float* __restrict__ b1,
    float* __restrict__ C1, int M1,
    const float* __restrict__ A2, const float* __restrict__ W2, const float* __restrict__ b2,
    float* __restrict__ C2, int M2,
    int K, int doRelu, int nb1)
{
    __shared__ char sh[28672];
    gemm_body(blockIdx.x, sh, A1, W1, b1, C1, nullptr, M1, A2, W2, b2, C2, nullptr, M2, K, doRelu, nb1);
}

// ---------------- GCN layer 1: warp/node, fp16 neighbor rows, paired CSR ----------------
__global__ void gather1_kernel() {
    int gw = (blockIdx.x * blockDim.x + threadIdx.x) >> 5;
    int lane = threadIdx.x & 31;
    if (gw >= NN) return;
    int start = g_off[gw];
    int deg = g_icnt[gw];
    float a0 = 0.f, a1 = 0.f;
    int nfull = deg & ~31;
    for (int j0 = 0; j0 < nfull; j0 += 32) {
        float2 pr = g_cpair[start + j0 + lane];
        int idx = __float_as_int(pr.x);
        float w = pr.y;
#pragma unroll
        for (int jj = 0; jj < 32; jj++) {
            int   s  = __shfl_sync(0xffffffffu, idx, jj);
            float wv = __shfl_sync(0xffffffffu, w, jj);
            float2 r = __half22float2(g_e0h[(size_t)s * 32 + lane]);
            a0 += wv * r.x;
            a1 += wv * r.y;
        }
    }
    int rem = deg - nfull;
    if (rem) {
        int idx = 0; float w = 0.f;
        if (lane < rem) {
            float2 pr = g_cpair[start + nfull + lane];
            idx = __float_as_int(pr.x);
            w = pr.y;
        }
        for (int jj = 0; jj < rem; jj++) {
            int   s  = __shfl_sync(0xffffffffu, idx, jj);
            float wv = __shfl_sync(0xffffffffu, w, jj);
            float2 r = __half22float2(g_e0h[(size_t)s * 32 + lane]);
            a0 += wv * r.x;
            a1 += wv * r.y;
        }
    }
    float sc = g_innorm[gw] * g_onorm[gw];
    float2 v = make_float2(a0 * sc, a1 * sc);
    *(float2*)(g_agg0s + (size_t)gw * 64 + 2 * lane) = v;
    g_agg0sh[(size_t)gw * 32 + lane] = __floats2half2_rn(v.x, v.y);
}

// ---------------- GCN layer 2 + final combine (fp16 neighbor rows) ----------------
__global__ void gather2_final_kernel(const float* __restrict__ side, float* __restrict__ out) {
    int gw = (blockIdx.x * blockDim.x + threadIdx.x) >> 5;
    int lane = threadIdx.x & 31;
    if (gw >= NN) return;
    int start = g_off[gw];
    int deg = g_icnt[gw];
    float a0 = 0.f, a1 = 0.f;
    int nfull = deg & ~31;
    for (int j0 = 0; j0 < nfull; j0 += 32) {
        int idx = __float_as_int(g_cpair[start + j0 + lane].x);
#pragma unroll
        for (int jj = 0; jj < 32; jj++) {
            int s = __shfl_sync(0xffffffffu, idx, jj);
            float2 r = __half22float2(g_agg0sh[(size_t)s * 32 + lane]);
            a0 += r.x;
            a1 += r.y;
        }
    }
    int rem = deg - nfull;
    if (rem) {
        int idx = 0;
        if (lane < rem) idx = __float_as_int(g_cpair[start + nfull + lane].x);
        for (int jj = 0; jj < rem; jj++) {
            int s = __shfl_sync(0xffffffffu, idx, jj);
            float2 r = __half22float2(g_agg0sh[(size_t)s * 32 + lane]);
            a0 += r.x;
            a1 += r.y;
        }
    }
    float inn3 = g_innorm[gw] * (1.0f / 3.0f);
    float half_rodeg = 0.5f * g_rodeg[gw];
    size_t base = (size_t)gw * 64 + 2 * lane;
    float2 e = *(const float2*)(g_e0 + base);
    float2 m = *(const float2*)(g_agg0s + base);
    float r0v = e.x + half_rodeg * m.x + inn3 * a0;
    float r1v = e.y + half_rodeg * m.y + inn3 * a1;
    if (gw >= NU) {
        float2 sd = *(const float2*)(side + (size_t)(gw - NU) * 64 + 2 * lane);
        r0v += sd.x;
        r1v += sd.y;
    }
    *(float2*)(out + base) = make_float2(r0v, r1v);
}

// ---------------- decode epilogue (float2 gathers) ----------------
__global__ void decode_kernel(const float* __restrict__ Tf, const float* __restrict__ Tcf,
                              const float* __restrict__ W1, const float* __restrict__ W2,
                              const int* __restrict__ userId, const int* __restrict__ posId,
                              const int* __restrict__ negId,
                              float* __restrict__ of, float* __restrict__ ocf) {
    __shared__ float w2s[64];
    __shared__ float w1l[64];
    int t = threadIdx.x;
    if (t < 64) {
        w2s[t] = W2[t];
        w1l[t] = W1[128 * 64 + t];
    }
    __syncthreads();

    int warp = t >> 5, lane = t & 31;
    int pair = blockIdx.x * 8 + warp;
    if (pair >= NP) return;

    int u  = userId[pair];
    int p  = posId[pair];
    int ng = negId[pair];

    float2 uv = *(const float2*)(g_xu + (size_t)u * 64 + 2 * lane);
    float2 pv = *(const float2*)(g_xi + (size_t)p * 64 + 2 * lane);
    float2 nv = *(const float2*)(g_xi + (size_t)ng * 64 + 2 * lane);
    float2 wl = *(const float2*)(w1l + 2 * lane);
    float2 w2 = *(const float2*)(w2s + 2 * lane);

    float tfp = Tf[pair],  tfn = Tf[pair + NP];
    float tcp = Tcf[pair], tcn = Tcf[pair + NP];

    auto combo = [&](float j0, float j1, float T) -> float {
        float x0 = uv.x + j0 + T * wl.x;
        float x1 = uv.y + j1 + T * wl.y;
        float e0 = x0 > 0.f ? x0 : (expf(x0) - 1.0f);
        float e1 = x1 > 0.f ? x1 : (expf(x1) - 1.0f);
        float s = e0 * w2.x + e1 * w2.y;
        s += __shfl_down_sync(0xffffffffu, s, 16);
        s += __shfl_down_sync(0xffffffffu, s, 8);
        s += __shfl_down_sync(0xffffffffu, s, 4);
        s += __shfl_down_sync(0xffffffffu, s, 2);
        s += __shfl_down_sync(0xffffffffu, s, 1);
        return s;
    };

    float rf_p = combo(pv.x, pv.y, tfp);
    float rf_n = combo(nv.x, nv.y, tfn);
    float rc_p = combo(pv.x, pv.y, tcp);
    float rc_n = combo(nv.x, nv.y, tcn);

    if (lane == 0) {
        of[pair]       = rf_p;
        of[pair + NP]  = rf_n;
        ocf[pair]      = rc_p;
        ocf[pair + NP] = rc_n;
    }
}

// ---------------- launch ----------------
extern "C" void kernel_launch(void* const* d_in, const int* in_sizes, int n_in,
                              void* d_out, int out_size) {
    const float* userF = (const float*)d_in[0];
    const float* itemF = (const float*)d_in[1];
    const float* side  = (const float*)d_in[2];
    const float* Tf    = (const float*)d_in[3];
    const float* Tcf   = (const float*)d_in[4];
    const float* Wu    = (const float*)d_in[5];
    const float* bu    = (const float*)d_in[6];
    const float* Wi    = (const float*)d_in[7];
    const float* bi    = (const float*)d_in[8];
    const float* W1    = (const float*)d_in[9];
    const float* b1    = (const float*)d_in[10];
    const float* W2    = (const float*)d_in[11];
    const int* esrc    = (const int*)d_in[12];
    const int* edst    = (const int*)d_in[13];
    const int* userId  = (const int*)d_in[14];
    const int* posId   = (const int*)d_in[15];
    const int* negId   = (const int*)d_in[16];

    float* out   = (float*)d_out;
    float* outI  = out + (size_t)NU * H;
    float* outLF = out + (size_t)NN * H;
    float* outLC = outLF + 2 * NP;

    float *pe0, *pxu, *pxi;
    __half2 *pe0h;
    cudaGetSymbolAddress((void**)&pe0, g_e0);
    cudaGetSymbolAddress((void**)&pe0h, g_e0h);
    cudaGetSymbolAddress((void**)&pxu, g_xu);
    cudaGetSymbolAddress((void**)&pxi, g_xi);

    int nb1 = (NU + 127) / 128;            // 391
    int nb2 = (NI + 127) / 128;            // 391
    int nbTot = nb1 + nb2;                 // 782
    int edgeBlocks = (NE / 4 + 255) / 256; // 1563

    clear_kernel<<<(NN + 255) / 256, 256>>>();

    // degree stage fused with first 300 GEMM blocks
    csr_gemm_kernel<<<300 + edgeBlocks, 256>>>(
        1, 300, 0, esrc, edst,
        userF, Wu, bu, pe0, pe0h, NU,
        itemF, Wi, bi, pe0 + (size_t)NU * H, pe0h + (size_t)NU * 32, NI,
        128, 1, nb1, nbTot);

    scan1_kernel<<<SCAN_NBLK, 256>>>();
    scan3_kernel<<<(NN + 255) / 256, 256>>>();

    // fill stage (writes (src, w) pairs) fused with remaining 482 GEMM blocks
    csr_gemm_kernel<<<482 + edgeBlocks, 256>>>(
        5, 482, 300, esrc, edst,
        userF, Wu, bu, pe0, pe0h, NU,
        itemF, Wi, bi, pe0 + (size_t)NU * H, pe0h + (size_t)NU * 32, NI,
        128, 1, nb1, nbTot);

    // GCN layers
    gather1_kernel<<<(NN * 32 + 255) / 256, 256>>>();
    gather2_final_kernel<<<(NN * 32 + 255) / 256, 256>>>(side, out);

    // per-node decode transforms
    gemm_dual<<<nbTot, 256>>>(out,  W1,           b1,      pxu, NU,
                              outI, W1 + 64 * 64, nullptr, pxi, NI,
                              64, 0, nb1);

    // decode epilogue
    decode_kernel<<<(NP + 7) / 8, 256>>>(Tf, Tcf, W1, W2, userId, posId, negId, outLF, outLC);
}

// round 16
// speedup vs baseline: 1.1267x; 1.0062x over previous
#include <cuda_runtime.h>
#include <cuda_fp16.h>
#include <math.h>

#define NU 50000
#define NI 50000
#define NN 100000
#define NE 1600000
#define NP 200000
#define H  64
#define SCAN_NBLK ((NN + 1023) / 1024)   // 98

// ---------------- device scratch ----------------
__device__ int   g_ocnt[NN];
__device__ int   g_icnt[NN];
__device__ float g_onorm[NN];
__device__ float g_innorm[NN];
__device__ float g_rodeg[NN];               // sqrt(max(out_deg,1))
__device__ int   g_off[NN];
__device__ int   g_cur[NN];
__device__ int   g_bsum[SCAN_NBLK];
__device__ float2 g_cpair[NE];              // (src as int bits, onorm[src])
__device__ float g_e0[(size_t)NN * H];
__device__ __half2 g_e0h[(size_t)NN * 32];      // fp16 mirror of e0 (gather reads)
__device__ float g_agg0s[(size_t)NN * H];   // layer-1 out, prescaled by onorm (fp32)
__device__ __half2 g_agg0sh[(size_t)NN * 32];   // fp16 mirror (gather reads)
__device__ float g_xu[(size_t)NU * H];
__device__ float g_xi[(size_t)NI * H];

// ---------------- tf32 helpers ----------------
__device__ __forceinline__ float to_tf32(float x) {
    float r;
    asm("cvt.rna.tf32.f32 %0, %1;" : "=f"(r) : "f"(x));
    return r;
}

__device__ __forceinline__ void mma_tf32(float c[4],
                                         unsigned a0, unsigned a1, unsigned a2, unsigned a3,
                                         unsigned b0, unsigned b1) {
    asm volatile(
        "mma.sync.aligned.m16n8k8.row.col.f32.tf32.tf32.f32 "
        "{%0,%1,%2,%3},{%4,%5,%6,%7},{%8,%9},{%0,%1,%2,%3};"
        : "+f"(c[0]), "+f"(c[1]), "+f"(c[2]), "+f"(c[3])
        : "r"(a0), "r"(a1), "r"(a2), "r"(a3), "r"(b0), "r"(b1));
}

// ---------------- tensor-core GEMM body (tf32 mma, fp32 accum) ----------------
// C[M x 64] = A[M x K] @ W[K x 64]; 128x64 block tile, 8 warps (m16 each).
// sh layout: Ws[2][16][88] at 0 (11264B), As[2][16][136] at 11264 (17408B). Total 28672B.
#define WS_STRIDE 88
#define AS_STRIDE 136
__device__ __forceinline__ void gemm_body(
    int gb, char* sh,
    const float* __restrict__ A1, const float* __restrict__ W1, const float* __restrict__ b1,
    float* __restrict__ C1, __half2* __restrict__ H1, int M1,
    const float* __restrict__ A2, const float* __restrict__ W2, const float* __restrict__ b2,
    float* __restrict__ C2, __half2* __restrict__ H2, int M2,
    int K, int doRelu, int nb1)
{
    float (*Ws)[16][WS_STRIDE] = (float(*)[16][WS_STRIDE])sh;
    float (*As)[16][AS_STRIDE] = (float(*)[16][AS_STRIDE])(sh + 11264);

    const float* A; const float* W; const float* bias; float* C; __half2* halfC; int M, bm0;
    if (gb < nb1) {
        A = A1; W = W1; bias = b1; C = C1; halfC = H1; M = M1; bm0 = gb * 128;
    } else {
        A = A2; W = W2; bias = b2; C = C2; halfC = H2; M = M2; bm0 = (gb - nb1) * 128;
    }

    int t = threadIdx.x;
    int wk = t >> 4;          // W-tile k row (0..15)
    int wc = t & 15;          // W-tile col quad
    int lrow = t >> 1;        // A-tile row (0..127)
    int lq = (t & 1) * 8;     // A-tile k offset
    int row = bm0 + lrow;
    bool rv = row < M;
    const float* Ar = A + (size_t)row * K;

    float4 p0 = make_float4(0.f, 0.f, 0.f, 0.f), p1 = p0, wv = p0;

#define FETCHA(k0) do { \
    if (rv) { p0 = *(const float4*)(Ar + (k0) + lq); p1 = *(const float4*)(Ar + (k0) + lq + 4); } \
} while (0)
#define FETCHW(k0) do { wv = *(const float4*)(W + (size_t)((k0) + wk) * 64 + wc * 4); } while (0)
#define STAGEA(buf) do { \
    As[buf][lq + 0][lrow] = to_tf32(p0.x); As[buf][lq + 1][lrow] = to_tf32(p0.y); \
    As[buf][lq + 2][lrow] = to_tf32(p0.z); As[buf][lq + 3][lrow] = to_tf32(p0.w); \
    As[buf][lq + 4][lrow] = to_tf32(p1.x); As[buf][lq + 5][lrow] = to_tf32(p1.y); \
    As[buf][lq + 6][lrow] = to_tf32(p1.z); As[buf][lq + 7][lrow] = to_tf32(p1.w); \
} while (0)
#define STAGEW(buf) do { \
    Ws[buf][wk][wc * 4 + 0] = to_tf32(wv.x); Ws[buf][wk][wc * 4 + 1] = to_tf32(wv.y); \
    Ws[buf][wk][wc * 4 + 2] = to_tf32(wv.z); Ws[buf][wk][wc * 4 + 3] = to_tf32(wv.w); \
} while (0)

    FETCHA(0); FETCHW(0);
    STAGEA(0); STAGEW(0);
    __syncthreads();

    float acc[8][4];
#pragma unroll
    for (int i = 0; i < 8; i++)
#pragma unroll
        for (int j = 0; j < 4; j++) acc[i][j] = 0.f;

    int warp = t >> 5, lane = t & 31;
    int gid = lane >> 2;      // 0..7
    int tig = lane & 3;       // 0..3
    int warpRow = warp * 16;
    int nt = K >> 4;

    for (int tile = 0; tile < nt; tile++) {
        int buf = tile & 1;
        if (tile + 1 < nt) { FETCHA((tile + 1) << 4); FETCHW((tile + 1) << 4); }

#pragma unroll
        for (int ks = 0; ks < 16; ks += 8) {
            unsigned a0 = __float_as_uint(As[buf][ks + tig    ][warpRow + gid]);
            unsigned a1 = __float_as_uint(As[buf][ks + tig    ][warpRow + gid + 8]);
            unsigned a2 = __float_as_uint(As[buf][ks + tig + 4][warpRow + gid]);
            unsigned a3 = __float_as_uint(As[buf][ks + tig + 4][warpRow + gid + 8]);
#pragma unroll
            for (int n = 0; n < 8; n++) {
                unsigned b0 = __float_as_uint(Ws[buf][ks + tig    ][n * 8 + gid]);
                unsigned b1 = __float_as_uint(Ws[buf][ks + tig + 4][n * 8 + gid]);
                mma_tf32(acc[n], a0, a1, a2, a3, b0, b1);
            }
        }

        if (tile + 1 < nt) {
            __syncthreads();
            STAGEA((tile + 1) & 1);
            STAGEW((tile + 1) & 1);
            __syncthreads();
        }
    }

    // epilogue: c0/c1 -> row warpRow+gid, cols 2*tig,2*tig+1 of each n-tile; c2/c3 -> row+8
    int r0 = bm0 + warpRow + gid;
    int r1 = r0 + 8;
#pragma unroll
    for (int n = 0; n < 8; n++) {
        int col = n * 8 + 2 * tig;
        float bx = 0.f, by = 0.f;
        if (bias) { float2 bb = *(const float2*)(bias + col); bx = bb.x; by = bb.y; }
        float v0 = acc[n][0] + bx, v1 = acc[n][1] + by;
        float v2 = acc[n][2] + bx, v3 = acc[n][3] + by;
        if (doRelu) {
            v0 = fmaxf(v0, 0.f); v1 = fmaxf(v1, 0.f);
            v2 = fmaxf(v2, 0.f); v3 = fmaxf(v3, 0.f);
        }
        if (r0 < M) {
            *(float2*)(C + (size_t)r0 * 64 + col) = make_float2(v0, v1);
            if (halfC) halfC[(size_t)r0 * 32 + col / 2] = __floats2half2_rn(v0, v1);
        }
        if (r1 < M) {
            *(float2*)(C + (size_t)r1 * 64 + col) = make_float2(v2, v3);
            if (halfC) halfC[(size_t)r1 * 32 + col / 2] = __floats2half2_rn(v2, v3);
        }
    }
#undef FETCHA
#undef FETCHW
#undef STAGEA
#undef STAGEW
}

// ---------------- fused edge-stage + GEMM-chunk co-kernel ----------------
// stage 1 = degree count; stage 5 = CSR fill writing (src, onorm[src]) pairs
__global__ void __launch_bounds__(256, 3) csr_gemm_kernel(
    int stage, int nGemm, int gemmStart,
    const int* __restrict__ esrc, const int* __restrict__ edst,
    const float* __restrict__ A1, const float* __restrict__ W1, const float* __restrict__ b1,
    float* __restrict__ C1, __half2* __restrict__ H1, int M1,
    const float* __restrict__ A2, const float* __restrict__ W2, const float* __restrict__ b2,
    float* __restrict__ C2, __half2* __restrict__ H2, int M2,
    int K, int doRelu, int nb1, int nbTot)
{
    __shared__ char sh[28672];
    int tid = threadIdx.x;

    if ((int)blockIdx.x < nGemm) {
        int gb = gemmStart + blockIdx.x;
        if (gb < nbTot)
            gemm_body(gb, sh, A1, W1, b1, C1, H1, M1, A2, W2, b2, C2, H2, M2, K, doRelu, nb1);
        return;
    }
    int cb = blockIdx.x - nGemm;
    int base = (cb * 256 + tid) * 4;
    if (base >= NE) return;

    int4 s4 = *(const int4*)(esrc + base);
    int4 d4 = *(const int4*)(edst + base);
    if (stage == 1) {
        atomicAdd(&g_ocnt[s4.x], 1); atomicAdd(&g_icnt[d4.x], 1);
        atomicAdd(&g_ocnt[s4.y], 1); atomicAdd(&g_icnt[d4.y], 1);
        atomicAdd(&g_ocnt[s4.z], 1); atomicAdd(&g_icnt[d4.z], 1);
        atomicAdd(&g_ocnt[s4.w], 1); atomicAdd(&g_icnt[d4.w], 1);
    } else {
        float wx = g_onorm[s4.x], wy = g_onorm[s4.y];
        float wz = g_onorm[s4.z], ww = g_onorm[s4.w];
        g_cpair[atomicAdd(&g_cur[d4.x], 1)] = make_float2(__int_as_float(s4.x), wx);
        g_cpair[atomicAdd(&g_cur[d4.y], 1)] = make_float2(__int_as_float(s4.y), wy);
        g_cpair[atomicAdd(&g_cur[d4.z], 1)] = make_float2(__int_as_float(s4.z), wz);
        g_cpair[atomicAdd(&g_cur[d4.w], 1)] = make_float2(__int_as_float(s4.w), ww);
    }
}

// ---------------- standalone small kernels ----------------
__global__ void clear_kernel() {
    int i = blockIdx.x * blockDim.x + threadIdx.x;
    if (i < NN) { g_ocnt[i] = 0; g_icnt[i] = 0; }
}

__global__ void scan1_kernel() {
    __shared__ int wsum[8];
    int tid = threadIdx.x;
    int base = blockIdx.x * 1024 + tid * 4;
    int v0 = (base + 0 < NN) ? g_icnt[base + 0] : 0;
    int v1 = (base + 1 < NN) ? g_icnt[base + 1] : 0;
    int v2 = (base + 2 < NN) ? g_icnt[base + 2] : 0;
    int v3 = (base + 3 < NN) ? g_icnt[base + 3] : 0;
    int s1 = v0, s2 = v0 + v1, s3 = v0 + v1 + v2, s = s3 + v3;
    int lane = tid & 31, wp = tid >> 5;
    int incl = s;
#pragma unroll
    for (int o = 1; o < 32; o <<= 1) {
        int n = __shfl_up_sync(0xffffffffu, incl, o);
        if (lane >= o) incl += n;
    }
    if (lane == 31) wsum[wp] = incl;
    __syncthreads();
    int wbase = 0;
    for (int k = 0; k < wp; k++) wbase += wsum[k];
    int et = wbase + incl - s;
    if (base + 0 < NN) g_off[base + 0] = et;
    if (base + 1 < NN) g_off[base + 1] = et + s1;
    if (base + 2 < NN) g_off[base + 2] = et + s2;
    if (base + 3 < NN) g_off[base + 3] = et + s3;
    if (tid == 255) g_bsum[blockIdx.x] = wbase + incl;
}

__global__ void scan3_kernel() {
    __shared__ int sboff[SCAN_NBLK];
    __shared__ int wsum[4];
    int tid = threadIdx.x;
    if (tid < 128) {
        int v = (tid < SCAN_NBLK) ? g_bsum[tid] : 0;
        int lane = tid & 31, wp = tid >> 5;
        int incl = v;
#pragma unroll
        for (int o = 1; o < 32; o <<= 1) {
            int n = __shfl_up_sync(0xffffffffu, incl, o);
            if (lane >= o) incl += n;
        }
        if (lane == 31) wsum[wp] = incl;
        __syncthreads();
        int wbase = 0;
        for (int k = 0; k < wp; k++) wbase += wsum[k];
        if (tid < SCAN_NBLK) sboff[tid] = wbase + incl - v;
    } else {
        __syncthreads();
    }
    __syncthreads();
    int i = blockIdx.x * blockDim.x + tid;
    if (i < NN) {
        int o = g_off[i] + sboff[i >> 10];
        g_off[i] = o;
        g_cur[i] = o;
        float od = fmaxf((float)g_ocnt[i], 1.0f);
        g_onorm[i]  = rsqrtf(od);
        g_rodeg[i]  = sqrtf(od);
        g_innorm[i] = rsqrtf(fmaxf((float)g_icnt[i], 1.0f));
    }
}

// ---------------- plain dual GEMM ----------------
__global__ void __launch_bounds__(256, 3) gemm_dual(
    const float* __restrict__ A1, const float* __restrict__ W1, const float* __restrict__ b1,
    float* __restrict__ C1, int M1,
    const float* __restrict__ A2, const float* __restrict__ W2, const float* __restrict__ b2,
    float* __restrict__ C2, int M2,
    int K, int doRelu, int nb1)
{
    __shared__ char sh[28672];
    gemm_body(blockIdx.x, sh, A1, W1, b1, C1, nullptr, M1, A2, W2, b2, C2, nullptr, M2, K, doRelu, nb1);
}

// ---------------- GCN layer 1: warp/node, fp16 neighbor rows, paired CSR ----------------
__global__ void gather1_kernel() {
    int gw = (blockIdx.x * blockDim.x + threadIdx.x) >> 5;
    int lane = threadIdx.x & 31;
    if (gw >= NN) return;
    int start = g_off[gw];
    int deg = g_icnt[gw];
    float a0 = 0.f, a1 = 0.f;
    int nfull = deg & ~31;
    for (int j0 = 0; j0 < nfull; j0 += 32) {
        float2 pr = g_cpair[start + j0 + lane];
        int idx = __float_as_int(pr.x);
        float w = pr.y;
#pragma unroll
        for (int jj = 0; jj < 32; jj++) {
            int   s  = __shfl_sync(0xffffffffu, idx, jj);
            float wv = __shfl_sync(0xffffffffu, w, jj);
            float2 r = __half22float2(g_e0h[(size_t)s * 32 + lane]);
            a0 += wv * r.x;
            a1 += wv * r.y;
        }
    }
    int rem = deg - nfull;
    if (rem) {
        int idx = 0; float w = 0.f;
        if (lane < rem) {
            float2 pr = g_cpair[start + nfull + lane];
            idx = __float_as_int(pr.x);
            w = pr.y;
        }
        for (int jj = 0; jj < rem; jj++) {
            int   s  = __shfl_sync(0xffffffffu, idx, jj);
            float wv = __shfl_sync(0xffffffffu, w, jj);
            float2 r = __half22float2(g_e0h[(size_t)s * 32 + lane]);
            a0 += wv * r.x;
            a1 += wv * r.y;
        }
    }
    float sc = g_innorm[gw] * g_onorm[gw];
    float2 v = make_float2(a0 * sc, a1 * sc);
    *(float2*)(g_agg0s + (size_t)gw * 64 + 2 * lane) = v;
    g_agg0sh[(size_t)gw * 32 + lane] = __floats2half2_rn(v.x, v.y);
}

// ---------------- GCN layer 2 + final combine (fp16 neighbor rows) ----------------
__global__ void gather2_final_kernel(const float* __restrict__ side, float* __restrict__ out) {
    int gw = (blockIdx.x * blockDim.x + threadIdx.x) >> 5;
    int lane = threadIdx.x & 31;
    if (gw >= NN) return;
    int start = g_off[gw];
    int deg = g_icnt[gw];
    float a0 = 0.f, a1 = 0.f;
    int nfull = deg & ~31;
    for (int j0 = 0; j0 < nfull; j0 += 32) {
        int idx = __float_as_int(g_cpair[start + j0 + lane].x);
#pragma unroll
        for (int jj = 0; jj < 32; jj++) {
            int s = __shfl_sync(0xffffffffu, idx, jj);
            float2 r = __half22float2(g_agg0sh[(size_t)s * 32 + lane]);
            a0 += r.x;
            a1 += r.y;
        }
    }
    int rem = deg - nfull;
    if (rem) {
        int idx = 0;
        if (lane < rem) idx = __float_as_int(g_cpair[start + nfull + lane].x);
        for (int jj = 0; jj < rem; jj++) {
            int s = __shfl_sync(0xffffffffu, idx, jj);
            float2 r = __half22float2(g_agg0sh[(size_t)s * 32 + lane]);
            a0 += r.x;
            a1 += r.y;
        }
    }
    float inn3 = g_innorm[gw] * (1.0f / 3.0f);
    float half_rodeg = 0.5f * g_rodeg[gw];
    size_t base = (size_t)gw * 64 + 2 * lane;
    float2 e = *(const float2*)(g_e0 + base);
    float2 m = *(const float2*)(g_agg0s + base);
    float r0v = e.x + half_rodeg * m.x + inn3 * a0;
    float r1v = e.y + half_rodeg * m.y + inn3 * a1;
    if (gw >= NU) {
        float2 sd = *(const float2*)(side + (size_t)(gw - NU) * 64 + 2 * lane);
        r0v += sd.x;
        r1v += sd.y;
    }
    *(float2*)(out + base) = make_float2(r0v, r1v);
}

// ---------------- decode epilogue (float2 gathers) ----------------
__global__ void decode_kernel(const float* __restrict__ Tf, const float* __restrict__ Tcf,
                              const float* __restrict__ W1, const float* __restrict__ W2,
                              const int* __restrict__ userId, const int* __restrict__ posId,
                              const int* __restrict__ negId,
                              float* __restrict__ of, float* __restrict__ ocf) {
    __shared__ float w2s[64];
    __shared__ float w1l[64];
    int t = threadIdx.x;
    if (t < 64) {
        w2s[t] = W2[t];
        w1l[t] = W1[128 * 64 + t];
    }
    __syncthreads();

    int warp = t >> 5, lane = t & 31;
    int pair = blockIdx.x * 8 + warp;
    if (pair >= NP) return;

    int u  = userId[pair];
    int p  = posId[pair];
    int ng = negId[pair];

    float2 uv = *(const float2*)(g_xu + (size_t)u * 64 + 2 * lane);
    float2 pv = *(const float2*)(g_xi + (size_t)p * 64 + 2 * lane);
    float2 nv = *(const float2*)(g_xi + (size_t)ng * 64 + 2 * lane);
    float2 wl = *(const float2*)(w1l + 2 * lane);
    float2 w2 = *(const float2*)(w2s + 2 * lane);

    float tfp = Tf[pair],  tfn = Tf[pair + NP];
    float tcp = Tcf[pair], tcn = Tcf[pair + NP];

    auto combo = [&](float j0, float j1, float T) -> float {
        float x0 = uv.x + j0 + T * wl.x;
        float x1 = uv.y + j1 + T * wl.y;
        float e0 = x0 > 0.f ? x0 : (expf(x0) - 1.0f);
        float e1 = x1 > 0.f ? x1 : (expf(x1) - 1.0f);
        float s = e0 * w2.x + e1 * w2.y;
        s += __shfl_down_sync(0xffffffffu, s, 16);
        s += __shfl_down_sync(0xffffffffu, s, 8);
        s += __shfl_down_sync(0xffffffffu, s, 4);
        s += __shfl_down_sync(0xffffffffu, s, 2);
        s += __shfl_down_sync(0xffffffffu, s, 1);
        return s;
    };

    float rf_p = combo(pv.x, pv.y, tfp);
    float rf_n = combo(nv.x, nv.y, tfn);
    float rc_p = combo(pv.x, pv.y, tcp);
    float rc_n = combo(nv.x, nv.y, tcn);

    if (lane == 0) {
        of[pair]       = rf_p;
        of[pair + NP]  = rf_n;
        ocf[pair]      = rc_p;
        ocf[pair + NP] = rc_n;
    }
}

// ---------------- launch ----------------
extern "C" void kernel_launch(void* const* d_in, const int* in_sizes, int n_in,
                              void* d_out, int out_size) {
    const float* userF = (const float*)d_in[0];
    const float* itemF = (const float*)d_in[1];
    const float* side  = (const float*)d_in[2];
    const float* Tf    = (const float*)d_in[3];
    const float* Tcf   = (const float*)d_in[4];
    const float* Wu    = (const float*)d_in[5];
    const float* bu    = (const float*)d_in[6];
    const float* Wi    = (const float*)d_in[7];
    const float* bi    = (const float*)d_in[8];
    const float* W1    = (const float*)d_in[9];
    const float* b1    = (const float*)d_in[10];
    const float* W2    = (const float*)d_in[11];
    const int* esrc    = (const int*)d_in[12];
    const int* edst    = (const int*)d_in[13];
    const int* userId  = (const int*)d_in[14];
    const int* posId   = (const int*)d_in[15];
    const int* negId   = (const int*)d_in[16];

    float* out   = (float*)d_out;
    float* outI  = out + (size_t)NU * H;
    float* outLF = out + (size_t)NN * H;
    float* outLC = outLF + 2 * NP;

    float *pe0, *pxu, *pxi;
    __half2 *pe0h;
    cudaGetSymbolAddress((void**)&pe0, g_e0);
    cudaGetSymbolAddress((void**)&pe0h, g_e0h);
    cudaGetSymbolAddress((void**)&pxu, g_xu);
    cudaGetSymbolAddress((void**)&pxi, g_xi);

    int nb1 = (NU + 127) / 128;            // 391
    int nb2 = (NI + 127) / 128;            // 391
    int nbTot = nb1 + nb2;                 // 782
    int edgeBlocks = (NE / 4 + 255) / 256; // 1563

    clear_kernel<<<(NN + 255) / 256, 256>>>();

    // degree stage fused with first 300 GEMM blocks
    csr_gemm_kernel<<<300 + edgeBlocks, 256>>>(
        1, 300, 0, esrc, edst,
        userF, Wu, bu, pe0, pe0h, NU,
        itemF, Wi, bi, pe0 + (size_t)NU * H, pe0h + (size_t)NU * 32, NI,
        128, 1, nb1, nbTot);

    scan1_kernel<<<SCAN_NBLK, 256>>>();
    scan3_kernel<<<(NN + 255) / 256, 256>>>();

    // fill stage (writes (src, w) pairs) fused with remaining 482 GEMM blocks
    csr_gemm_kernel<<<482 + edgeBlocks, 256>>>(
        5, 482, 300, esrc, edst,
        userF, Wu, bu, pe0, pe0h, NU,
        itemF, Wi, bi, pe0 + (size_t)NU * H, pe0h + (size_t)NU * 32, NI,
        128, 1, nb1, nbTot);

    // GCN layers
    gather1_kernel<<<(NN * 32 + 255) / 256, 256>>>();
    gather2_final_kernel<<<(NN * 32 + 255) / 256, 256>>>(side, out);

    // per-node decode transforms
    gemm_dual<<<nbTot, 256>>>(out,  W1,           b1,      pxu, NU,
                              outI, W1 + 64 * 64, nullptr, pxi, NI,
                              64, 0, nb1);

    // decode epilogue
    decode_kernel<<<(NP + 7) / 8, 256>>>(Tf, Tcf, W1, W2, userId, posId, negId, outLF, outLC);
}